// round 1
// baseline (speedup 1.0000x reference)
#include <cuda_runtime.h>
#include <cstdint>

#define BB   128
#define SS   64
#define DD   32
#define ND   200000
#define NNZT 4000000
#define TN   256

// ---------------- device scratch (no allocations allowed) ----------------
__device__ float  g_s_set[BB * DD];
__device__ float  g_common[BB * DD];
__device__ float  g_row_a[ND];
__device__ float  g_diffacc[BB * DD];
__device__ float  g_sdiff[BB];
__device__ double g_bce;
__device__ double g_neg1;

// ---------------- packed f32x2 helpers ----------------
__device__ __forceinline__ unsigned long long pk2(float lo, float hi) {
    unsigned long long r;
    asm("mov.b64 %0, {%1, %2};" : "=l"(r) : "f"(lo), "f"(hi));
    return r;
}
__device__ __forceinline__ void ffma2(unsigned long long& acc,
                                      unsigned long long a, unsigned long long b) {
    asm("fma.rn.f32x2 %0, %1, %2, %0;" : "+l"(acc) : "l"(a), "l"(b));
}
__device__ __forceinline__ float hsum2(unsigned long long a, unsigned long long b) {
    unsigned long long s;
    asm("add.rn.f32x2 %0, %1, %2;" : "=l"(s) : "l"(a), "l"(b));
    float x, y;
    asm("mov.b64 {%0, %1}, %2;" : "=f"(x), "=f"(y) : "l"(s));
    return x + y;
}

// ---------------- kernel 0: zero accumulators ----------------
__global__ void k_init() {
    int i = blockIdx.x * blockDim.x + threadIdx.x;
    int stride = gridDim.x * blockDim.x;
    for (int j = i; j < ND; j += stride) g_row_a[j] = 0.f;
    if (i < BB * DD) g_diffacc[i] = 0.f;
    if (i < BB) g_sdiff[i] = 0.f;
    if (i == 0) { g_bce = 0.0; g_neg1 = 0.0; }
}

// ---------------- kernel 1: row_a = segment_sum(ddi_values, ddi_indices[0]) ----
__global__ void k_hist(const int* __restrict__ idx, const float* __restrict__ val) {
    int i = blockIdx.x * blockDim.x + threadIdx.x;
    int stride = gridDim.x * blockDim.x;
    for (int j = i; j < NNZT; j += stride)
        atomicAdd(&g_row_a[idx[j]], val[j]);
}

// ---------------- kernel 2: s_set (normalized) + common_embed ----------------
// one block per batch b, 64 threads (one per s)
__global__ void k_attn(const int* __restrict__ syms, const int* __restrict__ simidx,
                       const float* __restrict__ sym_emb,
                       const float* __restrict__ w, const float* __restrict__ bvec) {
    int b = blockIdx.x;
    int s = threadIdx.x;
    __shared__ float sw[DD];
    __shared__ float sl[SS];
    __shared__ float sred[SS][DD];
    __shared__ float smax, ssum;
    if (s < DD) sw[s] = w[s];
    float b0 = bvec[0];
    __syncthreads();

    // ---- phase A: s_set ----
    int sym = syms[b * SS + s];
    float x[DD];
    {
        const float4* rp = (const float4*)(sym_emb + (size_t)sym * DD);
#pragma unroll
        for (int q = 0; q < DD / 4; q++) {
            float4 v = rp[q];
            x[4 * q + 0] = v.x; x[4 * q + 1] = v.y; x[4 * q + 2] = v.z; x[4 * q + 3] = v.w;
        }
    }
    float lg = 0.f;
#pragma unroll
    for (int k = 0; k < DD; k++) lg += x[k] * sw[k];
    lg += b0;
    sl[s] = lg;
    __syncthreads();
    if (s == 0) { float m = sl[0]; for (int j = 1; j < SS; j++) m = fmaxf(m, sl[j]); smax = m; }
    __syncthreads();
    float e = expf(lg - smax);
    sl[s] = e;
    __syncthreads();
    if (s == 0) { float t = 0.f; for (int j = 0; j < SS; j++) t += sl[j]; ssum = t; }
    __syncthreads();
    float alpha = e / ssum;
#pragma unroll
    for (int k = 0; k < DD; k++) sred[s][k] = alpha * x[k];
    __syncthreads();
    if (s < DD) {
        float acc = 0.f;
        for (int j = 0; j < SS; j++) acc += sred[j][s];
        float sq = acc * acc;
#pragma unroll
        for (int off = 16; off; off >>= 1) sq += __shfl_xor_sync(0xffffffffu, sq, off);
        float nrm = fmaxf(sqrtf(sq), 1e-12f);
        g_s_set[b * DD + s] = acc / nrm;
    }
    __syncthreads();

    // ---- phase B: common_embed (position-indexed sym_emb quirk) ----
    int sb = simidx[b];
    int sym2 = syms[sb * SS + s];
    float vals = (float)(sym * sym2);   // < 2^24, exact
    float y[DD];
    {
        const float4* rp = (const float4*)(sym_emb + (size_t)s * DD);
#pragma unroll
        for (int q = 0; q < DD / 4; q++) {
            float4 v = rp[q];
            y[4 * q + 0] = vals * v.x; y[4 * q + 1] = vals * v.y;
            y[4 * q + 2] = vals * v.z; y[4 * q + 3] = vals * v.w;
        }
    }
    lg = 0.f;
#pragma unroll
    for (int k = 0; k < DD; k++) lg += y[k] * sw[k];
    lg += b0;
    sl[s] = lg;
    __syncthreads();
    if (s == 0) { float m = sl[0]; for (int j = 1; j < SS; j++) m = fmaxf(m, sl[j]); smax = m; }
    __syncthreads();
    e = expf(lg - smax);
    sl[s] = e;
    __syncthreads();
    if (s == 0) { float t = 0.f; for (int j = 0; j < SS; j++) t += sl[j]; ssum = t; }
    __syncthreads();
    alpha = e / ssum;
#pragma unroll
    for (int k = 0; k < DD; k++) sred[s][k] = alpha * y[k];
    __syncthreads();
    if (s < DD) {
        float acc = 0.f;
        for (int j = 0; j < SS; j++) acc += sred[j][s];
        g_common[b * DD + s] = acc;   // not normalized
    }
}

// ---------------- kernel 3: fused mainloop ----------------
// 256 threads, thread t owns drug n = blockIdx.x*TN + t; loop over b (warp-staggered)
#define SD_STRIDE (TN + 1)
__global__ void __launch_bounds__(256) k_main(
    const float* __restrict__ drugs, const int* __restrict__ simidx,
    const float* __restrict__ drug_emb, float* __restrict__ out) {
    extern __shared__ float smem[];
    float* sd    = smem;                    // [DD][TN+1] transposed d tile
    float* s_s   = sd + DD * SD_STRIDE;     // [BB*DD]
    float* s_c   = s_s + BB * DD;           // [BB*DD]
    float* s_acc = s_c + BB * DD;           // [BB*DD] diff-embed accumulator
    float* s_sd  = s_acc + BB * DD;         // [BB]
    float* s_red = s_sd + BB;               // [256]
    int*   s_sim = (int*)(s_red + 256);     // [BB]

    int tid = threadIdx.x;
    int n0 = blockIdx.x * TN;
    int n = n0 + tid;
    bool valid = (n < ND);

    for (int i = tid; i < BB * DD; i += 256) {
        s_s[i] = g_s_set[i];
        s_c[i] = g_common[i];
        s_acc[i] = 0.f;
    }
    if (tid < BB) { s_sim[tid] = simidx[tid]; s_sd[tid] = 0.f; }

    // coalesced tile load of drug_emb rows n0+1 .. n0+TN into transposed smem
    for (int i = tid; i < TN * DD; i += 256) {
        int nl = i >> 5, k = i & 31;
        int gn = n0 + nl;
        float v = (gn < ND) ? drug_emb[(size_t)(gn + 1) * DD + k] : 0.f;
        sd[k * SD_STRIDE + nl] = v;
    }
    __syncthreads();

    // per-thread d vector: normalize, write back, pack to f32x2 regs
    float dreg[DD];
    float sqs = 0.f;
#pragma unroll
    for (int k = 0; k < DD; k++) { float v = sd[k * SD_STRIDE + tid]; dreg[k] = v; sqs += v * v; }
    float inv = 1.0f / fmaxf(sqrtf(sqs), 1e-12f);
#pragma unroll
    for (int k = 0; k < DD; k++) { dreg[k] *= inv; sd[k * SD_STRIDE + tid] = dreg[k]; }
    unsigned long long d2[DD / 2];
#pragma unroll
    for (int k = 0; k < DD / 2; k++) d2[k] = pk2(dreg[2 * k], dreg[2 * k + 1]);
    __syncthreads();

    int warp = tid >> 5, lane = tid & 31;
    float colsum = 0.f, bce = 0.f;
    const unsigned long long* s_s2 = (const unsigned long long*)s_s;
    const unsigned long long* s_c2 = (const unsigned long long*)s_c;

    for (int it = 0; it < BB; it++) {
        int b = (it + (warp << 4)) & (BB - 1);   // distinct b per warp at all times (skew<16)
        float db = 0.f, ds = 0.f;
        if (valid) {
            db = drugs[(size_t)b * ND + n];
            ds = drugs[(size_t)s_sim[b] * ND + n];
        }
        // score dot: t = s_set[b] . d
        unsigned long long a0 = 0ull, a1 = 0ull;
#pragma unroll
        for (int k = 0; k < DD / 2; k += 2) {
            ffma2(a0, d2[k],     s_s2[b * (DD / 2) + k]);
            ffma2(a1, d2[k + 1], s_s2[b * (DD / 2) + k + 1]);
        }
        float t = hsum2(a0, a1);
        float e = __expf(-t);
        float prob = __fdividef(1.f, 1.f + e);
        float score = (t > 0.f) ? prob : 0.f;
        if (valid) out[(size_t)b * ND + n] = score;
        colsum += score;

        // z dot: z = common_embed[b] . d ; BCE term
        a0 = 0ull; a1 = 0ull;
#pragma unroll
        for (int k = 0; k < DD / 2; k += 2) {
            ffma2(a0, d2[k],     s_c2[b * (DD / 2) + k]);
            ffma2(a1, d2[k + 1], s_c2[b * (DD / 2) + k + 1]);
        }
        float z = hsum2(a0, a1);
        float cd = db * ds;
        float term = fmaxf(z, 0.f) - z * cd + log1pf(__expf(-fabsf(z)));
        if (valid) bce += term;

        // diff branch (binary): ballot-compacted vector adds
        float diff = fabsf(db - ds);   // 0 or 1
        unsigned m = __ballot_sync(0xffffffffu, diff != 0.f);
        if (m) {
            if (lane == 0) s_sd[b] += (float)__popc(m);
            float* accb = s_acc + b * DD + lane;
            unsigned mm = m;
            do {
                int j = __ffs(mm) - 1; mm &= (mm - 1);
                *accb += sd[lane * SD_STRIDE + (warp << 5) + j];
            } while (mm);
        }
        if ((it & 7) == 7) __syncthreads();   // bound warp skew below the b-stagger
    }

    // block reductions -> double global accumulators
    s_red[tid] = bce;
    __syncthreads();
    for (int st = 128; st; st >>= 1) {
        if (tid < st) s_red[tid] += s_red[tid + st];
        __syncthreads();
    }
    if (tid == 0) atomicAdd(&g_bce, (double)s_red[0]);
    __syncthreads();

    float v = valid ? colsum * g_row_a[n] : 0.f;
    s_red[tid] = v;
    __syncthreads();
    for (int st = 128; st; st >>= 1) {
        if (tid < st) s_red[tid] += s_red[tid + st];
        __syncthreads();
    }
    if (tid == 0) atomicAdd(&g_neg1, (double)s_red[0]);
    __syncthreads();

    for (int i = tid; i < BB * DD; i += 256) atomicAdd(&g_diffacc[i], s_acc[i]);
    if (tid < BB) atomicAdd(&g_sdiff[tid], s_sd[tid]);
}

// ---------------- kernel 4: scalars ----------------
__global__ void k_final(float* __restrict__ out) {
    int b = threadIdx.x;   // 128 threads
    __shared__ float sred[BB];
    float acc = 0.f;
    float sdv = g_sdiff[b] + 1e-6f;
#pragma unroll
    for (int k = 0; k < DD; k++) {
        float de = g_diffacc[b * DD + k] / sdv;
        float x = g_common[b * DD + k] * de;
        acc += 1.0f / (1.0f + __expf(-x));
    }
    sred[b] = acc;
    __syncthreads();
    for (int st = 64; st; st >>= 1) {
        if (b < st) sred[b] += sred[b + st];
        __syncthreads();
    }
    if (b == 0) {
        out[(size_t)BB * ND]     = (float)(g_bce / (double)((double)BB * (double)ND));
        out[(size_t)BB * ND + 1] = (float)(1e-6 * g_neg1 + 1e-4 * (double)sred[0]);
    }
}

// ---------------- launcher ----------------
extern "C" void kernel_launch(void* const* d_in, const int* in_sizes, int n_in,
                              void* d_out, int out_size) {
    const int*   syms     = (const int*)d_in[0];
    const float* drugs    = (const float*)d_in[1];
    const int*   simidx   = (const int*)d_in[2];
    const int*   ddi_idx  = (const int*)d_in[3];   // [2, NNZ]; row 0 used
    const float* ddi_val  = (const float*)d_in[4];
    const float* sym_emb  = (const float*)d_in[5];
    const float* drug_emb = (const float*)d_in[6];
    const float* attn_w   = (const float*)d_in[7];
    const float* attn_b   = (const float*)d_in[8];
    float* out = (float*)d_out;

    static bool attr_set = false;
    const int smem_bytes = (DD * SD_STRIDE + 3 * BB * DD + BB + 256) * 4 + BB * 4;
    if (!attr_set) {
        cudaFuncSetAttribute(k_main, cudaFuncAttributeMaxDynamicSharedMemorySize, smem_bytes);
        attr_set = true;
    }

    k_init<<<256, 256>>>();
    k_hist<<<2048, 256>>>(ddi_idx, ddi_val);
    k_attn<<<BB, SS>>>(syms, simidx, sym_emb, attn_w, attn_b);
    int nb = (ND + TN - 1) / TN;
    k_main<<<nb, 256, smem_bytes>>>(drugs, simidx, drug_emb, out);
    k_final<<<1, BB>>>(out);
}

// round 2
// speedup vs baseline: 1.5884x; 1.5884x over previous
#include <cuda_runtime.h>
#include <cuda_bf16.h>
#include <cstdint>

#define BB   128
#define SS   64
#define DD   32
#define ND   200000
#define NNZT 4000000
#define TN   256
#define SDS  258   // bf16 sd stride: (SDS/2)=129 odd -> conflict-free column reads

// ---------------- device scratch ----------------
__device__ float  g_s_set[BB * DD];
__device__ float  g_common[BB * DD];
__device__ float  g_row_a[ND];
__device__ float  g_colsum[ND];
__device__ float  g_diffacc[BB * DD];
__device__ float  g_sdiff[BB];
__device__ double g_bce;
__device__ double g_neg1;

// ---------------- packed f32x2 helpers ----------------
__device__ __forceinline__ unsigned long long pk2(float lo, float hi) {
    unsigned long long r;
    asm("mov.b64 %0, {%1, %2};" : "=l"(r) : "f"(lo), "f"(hi));
    return r;
}
__device__ __forceinline__ void ffma2(unsigned long long& acc,
                                      unsigned long long a, unsigned long long b) {
    asm("fma.rn.f32x2 %0, %1, %2, %0;" : "+l"(acc) : "l"(a), "l"(b));
}
__device__ __forceinline__ float hsum2(unsigned long long a, unsigned long long b) {
    unsigned long long s;
    asm("add.rn.f32x2 %0, %1, %2;" : "=l"(s) : "l"(a), "l"(b));
    float x, y;
    asm("mov.b64 {%0, %1}, %2;" : "=f"(x), "=f"(y) : "l"(s));
    return x + y;
}

// ---------------- kernel 0: zero accumulators ----------------
__global__ void k_init() {
    int i = blockIdx.x * blockDim.x + threadIdx.x;
    int stride = gridDim.x * blockDim.x;
    for (int j = i; j < ND; j += stride) g_row_a[j] = 0.f;
    if (i < BB * DD) g_diffacc[i] = 0.f;
    if (i < BB) g_sdiff[i] = 0.f;
    if (i == 0) { g_bce = 0.0; g_neg1 = 0.0; }
}

// ---------------- kernel 1: row_a = segment_sum ----------------
__global__ void k_hist(const int* __restrict__ idx, const float* __restrict__ val) {
    int i = blockIdx.x * blockDim.x + threadIdx.x;
    int stride = gridDim.x * blockDim.x;
    for (int j = i; j < NNZT; j += stride)
        atomicAdd(&g_row_a[idx[j]], val[j]);
}

// ---------------- kernel 2: s_set (normalized) + common_embed ----------------
__global__ void k_attn(const int* __restrict__ syms, const int* __restrict__ simidx,
                       const float* __restrict__ sym_emb,
                       const float* __restrict__ w, const float* __restrict__ bvec) {
    int b = blockIdx.x;
    int s = threadIdx.x;
    __shared__ float sw[DD];
    __shared__ float sl[SS];
    __shared__ float sred[SS][DD];
    __shared__ float smax, ssum;
    if (s < DD) sw[s] = w[s];
    float b0 = bvec[0];
    __syncthreads();

    // ---- phase A: s_set ----
    int sym = syms[b * SS + s];
    float x[DD];
    {
        const float4* rp = (const float4*)(sym_emb + (size_t)sym * DD);
#pragma unroll
        for (int q = 0; q < DD / 4; q++) {
            float4 v = rp[q];
            x[4 * q + 0] = v.x; x[4 * q + 1] = v.y; x[4 * q + 2] = v.z; x[4 * q + 3] = v.w;
        }
    }
    float lg = 0.f;
#pragma unroll
    for (int k = 0; k < DD; k++) lg += x[k] * sw[k];
    lg += b0;
    sl[s] = lg;
    __syncthreads();
    if (s == 0) { float m = sl[0]; for (int j = 1; j < SS; j++) m = fmaxf(m, sl[j]); smax = m; }
    __syncthreads();
    float e = expf(lg - smax);
    sl[s] = e;
    __syncthreads();
    if (s == 0) { float t = 0.f; for (int j = 0; j < SS; j++) t += sl[j]; ssum = t; }
    __syncthreads();
    float alpha = e / ssum;
#pragma unroll
    for (int k = 0; k < DD; k++) sred[s][k] = alpha * x[k];
    __syncthreads();
    if (s < DD) {
        float acc = 0.f;
        for (int j = 0; j < SS; j++) acc += sred[j][s];
        float sq = acc * acc;
#pragma unroll
        for (int off = 16; off; off >>= 1) sq += __shfl_xor_sync(0xffffffffu, sq, off);
        float nrm = fmaxf(sqrtf(sq), 1e-12f);
        g_s_set[b * DD + s] = acc / nrm;
    }
    __syncthreads();

    // ---- phase B: common_embed ----
    int sb = simidx[b];
    int sym2 = syms[sb * SS + s];
    float vals = (float)(sym * sym2);
    float y[DD];
    {
        const float4* rp = (const float4*)(sym_emb + (size_t)s * DD);
#pragma unroll
        for (int q = 0; q < DD / 4; q++) {
            float4 v = rp[q];
            y[4 * q + 0] = vals * v.x; y[4 * q + 1] = vals * v.y;
            y[4 * q + 2] = vals * v.z; y[4 * q + 3] = vals * v.w;
        }
    }
    lg = 0.f;
#pragma unroll
    for (int k = 0; k < DD; k++) lg += y[k] * sw[k];
    lg += b0;
    sl[s] = lg;
    __syncthreads();
    if (s == 0) { float m = sl[0]; for (int j = 1; j < SS; j++) m = fmaxf(m, sl[j]); smax = m; }
    __syncthreads();
    e = expf(lg - smax);
    sl[s] = e;
    __syncthreads();
    if (s == 0) { float t = 0.f; for (int j = 0; j < SS; j++) t += sl[j]; ssum = t; }
    __syncthreads();
    alpha = e / ssum;
#pragma unroll
    for (int k = 0; k < DD; k++) sred[s][k] = alpha * y[k];
    __syncthreads();
    if (s < DD) {
        float acc = 0.f;
        for (int j = 0; j < SS; j++) acc += sred[j][s];
        g_common[b * DD + s] = acc;
    }
}

// ---------------- kernel 3: fused mainloop ----------------
__global__ void __launch_bounds__(256, 3) k_main(
    const float* __restrict__ drugs, const int* __restrict__ simidx,
    const float* __restrict__ drug_emb, float* __restrict__ out) {
    extern __shared__ float smem[];
    __nv_bfloat16* sd16 = (__nv_bfloat16*)smem;         // [DD][SDS] bf16
    float* s_s   = smem + (DD * SDS) / 2;               // [BB*DD] fp32
    float* s_c   = s_s + BB * DD;
    float* s_acc = s_c + BB * DD;                       // [BB*DD] diff-embed acc
    float* s_sd  = s_acc + BB * DD;                     // [BB]
    float* s_red = s_sd + BB;                           // [256]
    int*   s_sim = (int*)(s_red + 256);                 // [BB]

    int tid = threadIdx.x;
    int n0 = blockIdx.x * TN;
    int n = n0 + tid;
    bool valid = (n < ND);

    for (int i = tid; i < BB * DD; i += 256) {
        s_s[i] = g_s_set[i];
        s_c[i] = g_common[i];
        s_acc[i] = 0.f;
    }
    if (tid < BB) { s_sim[tid] = simidx[tid]; s_sd[tid] = 0.f; }

    // per-thread d row load (float4 x8), normalize in regs
    float dreg[DD];
    {
        int gn = valid ? n : (ND - 1);
        const float4* rp = (const float4*)(drug_emb + (size_t)(gn + 1) * DD);
        float sqs = 0.f;
#pragma unroll
        for (int q = 0; q < DD / 4; q++) {
            float4 v = rp[q];
            dreg[4 * q + 0] = v.x; dreg[4 * q + 1] = v.y;
            dreg[4 * q + 2] = v.z; dreg[4 * q + 3] = v.w;
            sqs += v.x * v.x + v.y * v.y + v.z * v.z + v.w * v.w;
        }
        float inv = 1.0f / fmaxf(sqrtf(sqs), 1e-12f);
        if (!valid) inv = 0.f;
#pragma unroll
        for (int k = 0; k < DD; k++) dreg[k] *= inv;
    }
    // publish bf16 copy for the diff path
#pragma unroll
    for (int k = 0; k < DD; k++) sd16[k * SDS + tid] = __float2bfloat16(dreg[k]);

    unsigned long long d2[DD / 2];
#pragma unroll
    for (int k = 0; k < DD / 2; k++) d2[k] = pk2(dreg[2 * k], dreg[2 * k + 1]);
    __syncthreads();

    int warp = tid >> 5, lane = tid & 31;
    float colsum = 0.f, bce = 0.f;
    const unsigned long long* s_s2 = (const unsigned long long*)s_s;
    const unsigned long long* s_c2 = (const unsigned long long*)s_c;

    // software-pipelined drugs loads
    int b_cur = (warp << 4) & (BB - 1);
    float db = valid ? drugs[(size_t)b_cur * ND + n] : 0.f;
    float ds = valid ? drugs[(size_t)s_sim[b_cur] * ND + n] : 0.f;

    for (int it = 0; it < BB; it++) {
        int b = b_cur;
        int b_nxt = (it + 1 + (warp << 4)) & (BB - 1);
        float db_n = 0.f, ds_n = 0.f;
        if (it + 1 < BB && valid) {
            db_n = drugs[(size_t)b_nxt * ND + n];
            ds_n = drugs[(size_t)s_sim[b_nxt] * ND + n];
        }

        // interleaved dots: t = s_set[b].d  ;  z = common[b].d
        unsigned long long a0 = 0ull, a1 = 0ull, c0 = 0ull, c1 = 0ull;
#pragma unroll
        for (int k = 0; k < DD / 2; k += 2) {
            unsigned long long dk = d2[k], dk1 = d2[k + 1];
            ffma2(a0, dk,  s_s2[b * (DD / 2) + k]);
            ffma2(c0, dk,  s_c2[b * (DD / 2) + k]);
            ffma2(a1, dk1, s_s2[b * (DD / 2) + k + 1]);
            ffma2(c1, dk1, s_c2[b * (DD / 2) + k + 1]);
        }
        float t = hsum2(a0, a1);
        float z = hsum2(c0, c1);

        float e = __expf(-t);
        float prob = __fdividef(1.f, 1.f + e);
        float score = (t > 0.f) ? prob : 0.f;
        if (valid) out[(size_t)b * ND + n] = score;
        colsum += score;

        // BCE term: relu(z) - z*cd + log1p(exp(-|z|)), fast-log form
        float cd = db * ds;
        float az = fabsf(z);
        float soft = __logf(1.f + __expf(-az));   // ==0 exactly when __expf underflows
        float term = fmaxf(z, 0.f) - z * cd + soft;
        bce += valid ? term : 0.f;

        // diff branch: ballot-compacted bf16 adds (warp owns b via stagger)
        float diff = fabsf(db - ds);
        unsigned m = __ballot_sync(0xffffffffu, diff != 0.f);
        if (m) {
            if (lane == 0) s_sd[b] += (float)__popc(m);
            float* accb = s_acc + b * DD + lane;
            const __nv_bfloat16* col = sd16 + lane * SDS + (warp << 5);
            unsigned mm = m;
            do {
                int j = __ffs(mm) - 1; mm &= (mm - 1);
                *accb += __bfloat162float(col[j]);
            } while (mm);
        }

        db = db_n; ds = ds_n; b_cur = b_nxt;
        if ((it & 7) == 7) __syncthreads();   // bound warp skew below stagger gap
    }

    if (valid) g_colsum[n] = colsum;

    // bce block reduction -> double accumulator
    s_red[tid] = bce;
    __syncthreads();
    for (int st = 128; st; st >>= 1) {
        if (tid < st) s_red[tid] += s_red[tid + st];
        __syncthreads();
    }
    if (tid == 0) atomicAdd(&g_bce, (double)s_red[0]);
    __syncthreads();

    for (int i = tid; i < BB * DD; i += 256) atomicAdd(&g_diffacc[i], s_acc[i]);
    if (tid < BB) atomicAdd(&g_sdiff[tid], s_sd[tid]);
}

// ---------------- kernel 4: neg1 = dot(colsum, row_a) ----------------
__global__ void k_tail() {
    __shared__ float sred[256];
    int tid = threadIdx.x;
    int i = blockIdx.x * blockDim.x + tid;
    int stride = gridDim.x * blockDim.x;
    float acc = 0.f;
    for (int j = i; j < ND; j += stride) acc += g_colsum[j] * g_row_a[j];
    sred[tid] = acc;
    __syncthreads();
    for (int st = 128; st; st >>= 1) {
        if (tid < st) sred[tid] += sred[tid + st];
        __syncthreads();
    }
    if (tid == 0) atomicAdd(&g_neg1, (double)sred[0]);
}

// ---------------- kernel 5: scalars ----------------
__global__ void k_final(float* __restrict__ out) {
    int b = threadIdx.x;   // 128 threads
    __shared__ float sred[BB];
    float acc = 0.f;
    float sdv = g_sdiff[b] + 1e-6f;
#pragma unroll
    for (int k = 0; k < DD; k++) {
        float de = g_diffacc[b * DD + k] / sdv;
        float x = g_common[b * DD + k] * de;
        acc += 1.0f / (1.0f + __expf(-x));
    }
    sred[b] = acc;
    __syncthreads();
    for (int st = 64; st; st >>= 1) {
        if (b < st) sred[b] += sred[b + st];
        __syncthreads();
    }
    if (b == 0) {
        out[(size_t)BB * ND]     = (float)(g_bce / (double)((double)BB * (double)ND));
        out[(size_t)BB * ND + 1] = (float)(1e-6 * g_neg1 + 1e-4 * (double)sred[0]);
    }
}

// ---------------- launcher ----------------
extern "C" void kernel_launch(void* const* d_in, const int* in_sizes, int n_in,
                              void* d_out, int out_size) {
    const int*   syms     = (const int*)d_in[0];
    const float* drugs    = (const float*)d_in[1];
    const int*   simidx   = (const int*)d_in[2];
    const int*   ddi_idx  = (const int*)d_in[3];
    const float* ddi_val  = (const float*)d_in[4];
    const float* sym_emb  = (const float*)d_in[5];
    const float* drug_emb = (const float*)d_in[6];
    const float* attn_w   = (const float*)d_in[7];
    const float* attn_b   = (const float*)d_in[8];
    float* out = (float*)d_out;

    static bool attr_set = false;
    const int smem_bytes = (DD * SDS) * 2 + (3 * BB * DD + BB + 256) * 4 + BB * 4;
    if (!attr_set) {
        cudaFuncSetAttribute(k_main, cudaFuncAttributeMaxDynamicSharedMemorySize, smem_bytes);
        attr_set = true;
    }

    k_init<<<256, 256>>>();
    k_attn<<<BB, SS>>>(syms, simidx, sym_emb, attn_w, attn_b);
    int nb = (ND + TN - 1) / TN;
    k_main<<<nb, 256, smem_bytes>>>(drugs, simidx, drug_emb, out);
    k_hist<<<2048, 256>>>(ddi_idx, ddi_val);
    k_tail<<<256, 256>>>();
    k_final<<<1, BB>>>(out);
}